// round 16
// baseline (speedup 1.0000x reference)
#include <cuda_runtime.h>
#include <cuda_fp16.h>
#include <cstdint>
#include <math.h>

#define T_TOK 4096
#define HDIM  2048
#define IDIM  768
#define NEXP  16
#define N13   (2*IDIM)          // 1536
#define MAXSLOTS 10496
#define MAXTILES 96
#define GRID_TILES 80
#define W13_BYTES (NEXP*N13*(HDIM/4))   // 12582912
#define W2_BYTES  (NEXP*HDIM*(IDIM/4))  // 6291456

// ---------------- scratch (__device__ globals) --------------------------------
__device__ int   g_pad_off[NEXP+1];
__device__ int   g_tile_e[MAXTILES];
__device__ int   g_tile_m0[MAXTILES];
__device__ int   g_ntiles;
__device__ int   g_nslots;
__device__ int   g_token_eidx[T_TOK*2];
__device__ int   g_token_slot[T_TOK*2];
__device__ float g_token_wt[T_TOK*2];
__device__ __align__(256) uint8_t g_w13[W13_BYTES];   // interleaved: row 2j=gate_j, 2j+1=up_j
__device__ __align__(256) uint8_t g_w2 [W2_BYTES];
__device__ __align__(256) float   g_a13f[NEXP*HDIM];
__device__ __align__(256) float   g_a2f [NEXP*IDIM];
__device__ __align__(256) __half  g_xs [MAXSLOTS*HDIM];
__device__ __align__(256) __half  g_act[MAXSLOTS*IDIM];
__device__ __align__(256) float   g_down[MAXSLOTS*HDIM];

// ---------------- dtype-delivery detection ------------------------------------
__device__ __forceinline__ int detect_mode(const void* p, int lo) {
    const int*   pi = (const int*)p;
    const float* pf = (const float*)p;
    bool i32 = true, f32 = true;
    for (int j = 0; j < 8; j++) {
        int v = pi[j];
        if (v < lo || v > 255) i32 = false;
        float f = pf[j];
        if (!(f >= (float)lo - 0.5f && f <= 255.5f && f == rintf(f))) f32 = false;
    }
    if (i32) return 1;
    if (f32) return 2;
    return 0;
}
__device__ __forceinline__ uint32_t ldb(const void* p, long i, int mode) {
    if (mode == 1) return (uint32_t)((const int*)p)[i] & 0xFFu;
    if (mode == 2) return (uint32_t)(int)((const float*)p)[i] & 0xFFu;
    return (uint32_t)((const uint8_t*)p)[i];
}
__device__ __forceinline__ int ldq(const void* p, long i, int mode) {
    if (mode == 1) return ((const int*)p)[i];
    if (mode == 2) return (int)((const float*)p)[i];
    return (int)((const int8_t*)p)[i];
}

// ---------------- fused repack (+ g_xs zeroing) --------------------------------
#define RW13_BLKS (W13_BYTES/256)
#define RW2_BLKS  (W2_BYTES/256)
#define RA13_BLKS ((NEXP*HDIM)/256)
#define RA2_BLKS  ((NEXP*IDIM)/256)
#define ZX_BLKS   MAXSLOTS
#define REPACK_BLKS (RW13_BLKS + RW2_BLKS + RA13_BLKS + RA2_BLKS + ZX_BLKS)

__global__ void k_repack(const void* __restrict__ w13p, const void* __restrict__ w2p,
                         const void* __restrict__ a13q, const float* __restrict__ a13s,
                         const void* __restrict__ a2q,  const float* __restrict__ a2s) {
    __shared__ int s_mode;
    int bid = blockIdx.x, tid = threadIdx.x;
    if (bid < RW13_BLKS) {
        if (tid == 0) s_mode = detect_mode(w13p, 0);
        __syncthreads();
        long i = (long)bid * 256 + tid;
        int e   = (int)(i / (N13 * (HDIM/4)));
        int rem = (int)(i % (N13 * (HDIM/4)));
        int rp  = rem / (HDIM/4);
        int kb  = rem % (HDIM/4);
        int r   = (rp & 1) ? (IDIM + (rp >> 1)) : (rp >> 1);
        long src = ((long)e * N13 + r) * (HDIM/4) + kb;
        g_w13[i] = (uint8_t)ldb(w13p, src, s_mode);
    } else if (bid < RW13_BLKS + RW2_BLKS) {
        if (tid == 0) s_mode = detect_mode(w2p, 0);
        __syncthreads();
        long i = (long)(bid - RW13_BLKS) * 256 + tid;
        g_w2[i] = (uint8_t)ldb(w2p, i, s_mode);
    } else if (bid < RW13_BLKS + RW2_BLKS + RA13_BLKS) {
        if (tid == 0) s_mode = detect_mode(a13q, 1);
        __syncthreads();
        int i = (bid - RW13_BLKS - RW2_BLKS) * 256 + tid;
        g_a13f[i] = (float)ldq(a13q, i, s_mode) * a13s[0];
    } else if (bid < RW13_BLKS + RW2_BLKS + RA13_BLKS + RA2_BLKS) {
        if (tid == 0) s_mode = detect_mode(a2q, 1);
        __syncthreads();
        int i = (bid - RW13_BLKS - RW2_BLKS - RA13_BLKS) * 256 + tid;
        g_a2f[i] = (float)ldq(a2q, i, s_mode) * a2s[0];
    } else {
        int row = bid - (RW13_BLKS + RW2_BLKS + RA13_BLKS + RA2_BLKS);
        ((uint4*)g_xs)[(size_t)row * 256 + tid] = make_uint4(0, 0, 0, 0);
    }
}

// ---------------- single-block routing ----------------------------------------
__global__ __launch_bounds__(1024) void k_route(const float* __restrict__ logits) {
    __shared__ int s_cnt[NEXP];
    __shared__ int s_off[NEXP];
    int tid = threadIdx.x;
    if (tid < NEXP) s_cnt[tid] = 0;
    __syncthreads();
    int li0[4], li1[4];
    for (int it = 0; it < 4; it++) {
        int t = tid + it * 1024;
        float l[NEXP];
#pragma unroll
        for (int e = 0; e < NEXP; e++) l[e] = logits[t * NEXP + e];
        int i0 = 0; float b0 = l[0];
#pragma unroll
        for (int e = 1; e < NEXP; e++) if (l[e] > b0) { b0 = l[e]; i0 = e; }
        int i1 = -1; float b1 = -1e30f;
#pragma unroll
        for (int e = 0; e < NEXP; e++) if (e != i0 && l[e] > b1) { b1 = l[e]; i1 = e; }
        float w0 = 1.0f / (1.0f + expf(b1 - b0));
        g_token_eidx[2*t]   = i0;
        g_token_eidx[2*t+1] = i1;
        g_token_wt[2*t]     = w0;
        g_token_wt[2*t+1]   = 1.0f - w0;
        atomicAdd(&s_cnt[i0], 1);
        atomicAdd(&s_cnt[i1], 1);
        li0[it] = i0; li1[it] = i1;
    }
    __syncthreads();
    if (tid == 0) {
        int off = 0, tiles = 0;
        for (int e = 0; e < NEXP; e++) {
            g_pad_off[e] = off; s_off[e] = off;
            int nt = (s_cnt[e] + 127) >> 7;
            for (int j = 0; j < nt; j++) { g_tile_e[tiles] = e; g_tile_m0[tiles] = off + (j << 7); tiles++; }
            off += nt << 7;
        }
        g_pad_off[NEXP] = off;
        g_ntiles = tiles;
        g_nslots = off;
    }
    __syncthreads();
    if (tid < NEXP) s_cnt[tid] = 0;
    __syncthreads();
    for (int it = 0; it < 4; it++) {
        int t = tid + it * 1024;
        int r0 = atomicAdd(&s_cnt[li0[it]], 1);
        g_token_slot[2*t]   = s_off[li0[it]] + r0;
        int r1 = atomicAdd(&s_cnt[li1[it]], 1);
        g_token_slot[2*t+1] = s_off[li1[it]] + r1;
    }
}

__global__ void k_xs(const float* __restrict__ x) {
    int r = blockIdx.x;
    int t = r >> 1;
    int slot = g_token_slot[r];
    int e = g_token_eidx[r];
    const float* xr = x + (size_t)t * HDIM;
    const float* ar = g_a13f + (size_t)e * HDIM;
    __half* o = g_xs + (size_t)slot * HDIM;
    for (int j = threadIdx.x; j < HDIM; j += 256)
        o[j] = __float2half(xr[j] * ar[j]);
}

__global__ void k_combine(float* __restrict__ out) {
    int t = blockIdx.x;
    int s0 = g_token_slot[2*t], s1 = g_token_slot[2*t+1];
    float w0 = g_token_wt[2*t], w1 = g_token_wt[2*t+1];
    const float* d0 = g_down + (size_t)s0 * HDIM;
    const float* d1 = g_down + (size_t)s1 * HDIM;
    float* o = out + (size_t)t * HDIM;
    for (int j = threadIdx.x; j < HDIM; j += 256)
        o[j] = w0 * d0[j] + w1 * d1[j];
}

// ---------------- GEMM: fp16 A x ternary-2bit B -> f32, register B decode -----
// BM=128 BN=128 BK=32, 256 threads (8 warps, 4Mx2N), warp tile 32x64.
// A: cp.async double-buffered SMEM + ldmatrix. B: RAW packed words in SMEM
// (1KB/stage), decoded to mma fragments in registers via PRMT against pool
// 0x003C00BC (v=0 -> 0xBC00(-1), v=1 -> 0x0000, v=2 -> 0x3C00(+1)).
__device__ __forceinline__ void ldsm4(uint32_t& r0, uint32_t& r1, uint32_t& r2, uint32_t& r3,
                                      const void* p) {
    uint32_t a = (uint32_t)__cvta_generic_to_shared(p);
    asm volatile("ldmatrix.sync.aligned.m8n8.x4.shared.b16 {%0,%1,%2,%3},[%4];"
                 : "=r"(r0), "=r"(r1), "=r"(r2), "=r"(r3) : "r"(a));
}
__device__ __forceinline__ void mma16816(float* c, const uint32_t* a, const uint32_t* b) {
    asm volatile("mma.sync.aligned.m16n8k16.row.col.f32.f16.f16.f32 "
                 "{%0,%1,%2,%3},{%4,%5,%6,%7},{%8,%9},{%0,%1,%2,%3};"
                 : "+f"(c[0]), "+f"(c[1]), "+f"(c[2]), "+f"(c[3])
                 : "r"(a[0]), "r"(a[1]), "r"(a[2]), "r"(a[3]), "r"(b[0]), "r"(b[1]));
}
__device__ __forceinline__ float silu_f(float g) { return g / (1.0f + expf(-g)); }

template <int WHICH>  // 0: xs @ w13i^T -> silu-fused -> g_act.  1: act @ w2^T -> g_down.
__global__ __launch_bounds__(256, 2) void k_gemm() {
    constexpr int K = (WHICH == 0) ? HDIM : IDIM;
    constexpr int N = (WHICH == 0) ? N13  : HDIM;
    constexpr int KB = K / 4;
    constexpr int S  = K / 32;
    const __half*  A  = (WHICH == 0) ? g_xs  : g_act;
    const uint8_t* Bp = (WHICH == 0) ? g_w13 : g_w2;

    __shared__ __half   sA[2][128][40];
    __shared__ uint32_t sRawB[2][256];   // [buf][row*2 + word], 8B packed per row per stage

    int bx = blockIdx.x;
    if (bx >= g_ntiles) return;
    int e  = g_tile_e[bx];
    int m0 = g_tile_m0[bx];
    int n0 = blockIdx.y * 128;
    const uint8_t* Be = Bp + (size_t)e * N * KB;

    int tid = threadIdx.x;
    int w = tid >> 5, lane = tid & 31;
    int wm = w & 3, wn = w >> 2;
    int gid = lane >> 2, tig = lane & 3;
    int aRow = (lane & 7) + ((lane >> 3) & 1) * 8;
    int aCol = ((lane >> 4) & 1) * 8;
    int shB = 4 * tig;                   // bit shift for this thread's B values

    int ar0 = tid >> 2, ac0 = tid & 3;   // A cp.async mapping
    int br  = tid >> 1, bsel = tid & 1;  // B raw word mapping (row, word)
    const __half*  Abase = A + (size_t)m0 * K;
    const uint8_t* Brow  = Be + (size_t)(n0 + br) * KB;

    uint32_t pk;
    // prologue: stage 0
    {
#pragma unroll
        for (int i = 0; i < 2; i++) {
            int r = ar0 + i * 64;
            uint32_t dst = (uint32_t)__cvta_generic_to_shared(&sA[0][r][ac0 * 8]);
            const void* src = Abase + (size_t)r * K + ac0 * 8;
            asm volatile("cp.async.cg.shared.global [%0], [%1], 16;" :: "r"(dst), "l"(src));
        }
        asm volatile("cp.async.commit_group;");
        pk = *(const uint32_t*)(Brow + bsel * 4);
        sRawB[0][tid] = pk;              // index == row*2 + word == tid
    }
    asm volatile("cp.async.wait_group 0;");
    __syncthreads();

    float c[2][8][4] = {};

    for (int s = 0; s < S; s++) {
        int cur = s & 1, nxt = cur ^ 1;
        if (s + 1 < S) {
            int k0 = (s + 1) * 32;
#pragma unroll
            for (int i = 0; i < 2; i++) {
                int r = ar0 + i * 64;
                uint32_t dst = (uint32_t)__cvta_generic_to_shared(&sA[nxt][r][ac0 * 8]);
                const void* src = Abase + (size_t)r * K + k0 + ac0 * 8;
                asm volatile("cp.async.cg.shared.global [%0], [%1], 16;" :: "r"(dst), "l"(src));
            }
            asm volatile("cp.async.commit_group;");
            pk = *(const uint32_t*)(Brow + (k0 >> 2) + bsel * 4);
        }

#pragma unroll
        for (int kk = 0; kk < 32; kk += 16) {
            uint32_t af[2][4], bf[8][2];
#pragma unroll
            for (int mt = 0; mt < 2; mt++)
                ldsm4(af[mt][0], af[mt][1], af[mt][2], af[mt][3],
                      &sA[cur][wm * 32 + mt * 16 + aRow][kk + aCol]);
            // register B decode: one LDS.b32 (16 k-values of the row) + 2 PRMT
#pragma unroll
            for (int ns = 0; ns < 8; ns++) {
                int rr = wn * 64 + ns * 8 + gid;
                uint32_t wv = sRawB[cur][rr * 2 + (kk >> 4)];
                uint32_t t  = wv >> shB;
                bf[ns][0] = __byte_perm(0x003C00BCu, 0u,
                                        0x0101u | ((t & 3u) << 4) | ((t & 0xCu) << 10));
                uint32_t u = t >> 16;
                bf[ns][1] = __byte_perm(0x003C00BCu, 0u,
                                        0x0101u | ((u & 3u) << 4) | ((u & 0xCu) << 10));
            }
#pragma unroll
            for (int mt = 0; mt < 2; mt++)
#pragma unroll
                for (int ns = 0; ns < 8; ns++)
                    mma16816(c[mt][ns], af[mt], bf[ns]);
        }

        if (s + 1 < S) {
            asm volatile("cp.async.wait_group 0;");
            sRawB[nxt][tid] = pk;
        }
        __syncthreads();
    }

    if (WHICH == 0) {
        // interleaved cols: even=gate_j, odd=up_j; each thread's float2 is the pair
#pragma unroll
        for (int mt = 0; mt < 2; mt++)
#pragma unroll
            for (int ns = 0; ns < 8; ns++) {
                int col = n0 + wn * 64 + ns * 8 + tig * 2;
                int j = col >> 1;
                float al = __ldg(&g_a2f[(size_t)e * IDIM + j]);
                int row0 = m0 + wm * 32 + mt * 16 + gid;
                g_act[(size_t)row0 * IDIM + j] =
                    __float2half(silu_f(c[mt][ns][0]) * c[mt][ns][1] * al);
                g_act[(size_t)(row0 + 8) * IDIM + j] =
                    __float2half(silu_f(c[mt][ns][2]) * c[mt][ns][3] * al);
            }
    } else {
#pragma unroll
        for (int mt = 0; mt < 2; mt++)
#pragma unroll
            for (int ns = 0; ns < 8; ns++) {
                int row = m0 + wm * 32 + mt * 16 + gid;
                int col = n0 + wn * 64 + ns * 8 + tig * 2;
                *(float2*)(g_down + (size_t)row * N + col)       = make_float2(c[mt][ns][0], c[mt][ns][1]);
                *(float2*)(g_down + (size_t)(row + 8) * N + col) = make_float2(c[mt][ns][2], c[mt][ns][3]);
            }
    }
}

// ---------------- launch ------------------------------------------------------
extern "C" void kernel_launch(void* const* d_in, const int* in_sizes, int n_in,
                              void* d_out, int out_size) {
    const float* x      = nullptr;
    const float* logits = nullptr;
    const void*  w13p   = nullptr;
    const void*  a13q   = nullptr;
    const float* a13s   = nullptr;
    const void*  w2p    = nullptr;
    const void*  a2q    = nullptr;
    const float* a2s    = nullptr;
    for (int i = 0; i < n_in; i++) {
        long sz = in_sizes[i];
        void* p = d_in[i];
        if      (sz == 8388608)  x      = (const float*)p;
        else if (sz == 65536)    logits = (const float*)p;
        else if (sz == 12582912) w13p   = p;
        else if (sz == 32768)    a13q   = p;
        else if (sz == 6291456)  w2p    = p;
        else if (sz == 12288)    a2q    = p;
        else if (sz == 1) { if (!a13s) a13s = (const float*)p; else a2s = (const float*)p; }
    }
    float* out = (float*)d_out;

    k_repack <<<REPACK_BLKS, 256>>>(w13p, w2p, a13q, a13s, a2q, a2s);  // 0
    k_route  <<<1, 1024>>>(logits);                                     // 1
    k_xs     <<<T_TOK*2, 256>>>(x);                                     // 2
    k_gemm<0><<<dim3(GRID_TILES, N13 / 128), 256>>>();                  // 3  <- ncu lands here
    k_gemm<1><<<dim3(GRID_TILES, HDIM / 128), 256>>>();                 // 4
    k_combine<<<T_TOK, 256>>>(out);                                     // 5
}